// round 16
// baseline (speedup 1.0000x reference)
#include <cuda_runtime.h>
#include <cuda_bf16.h>
#include <cstdint>
typedef __nv_bfloat16 bf16;
typedef long long ll;

#define B_ 2
#define S_ 2048
#define H_ 1024
#define NH_ 16
#define M_ 512

// ---------- static scratch ----------
__device__ __align__(16) bf16 g_inH [8388608], g_inL [8388608];   // hs|mc pairs
__device__ __align__(16) bf16 g_wH  [3145728], g_wL  [3145728];   // Wq|Wk|Wv
__device__ __align__(16) bf16 g_wmH [1048576], g_wmL [1048576];   // Wmq|Wmk
__device__ __align__(16) bf16 g_wcH [524288],  g_wcL [524288];
__device__ __align__(16) bf16 g_wfH [1572864], g_wfL [1572864];
__device__ float g_b3 [3072];
__device__ float g_bm2[1024];
__device__ __align__(16) bf16 g_qkvH[12582912], g_qkvL[12582912]; // q|k|v pairs
__device__ __align__(16) bf16 g_mqkH[4194304],  g_mqkL[4194304];  // mq|mk pairs
__device__ float g_med [8388608];                                  // exp med scores
__device__ __align__(16) bf16 g_catH[6291456],  g_catL[6291456];  // cat pair
__device__ float g_x   [4194304];
__device__ float g_part[2097152];
__device__ float g_minv[4096];
__device__ float g_pinv[65536];

// ---------- helpers ----------
__device__ __forceinline__ uint32_t smem_to_u32(const void* p) {
    uint32_t a;
    asm("{ .reg .u64 t; cvta.to.shared.u64 t, %1; cvt.u32.u64 %0, t; }" : "=r"(a) : "l"(p));
    return a;
}
__device__ __forceinline__ void ldmx4(uint32_t* r, uint32_t a) {
    asm volatile("ldmatrix.sync.aligned.m8n8.x4.shared.b16 {%0,%1,%2,%3}, [%4];"
        : "=r"(r[0]), "=r"(r[1]), "=r"(r[2]), "=r"(r[3]) : "r"(a));
}
__device__ __forceinline__ void ldmx4t(uint32_t* r, uint32_t a) {
    asm volatile("ldmatrix.sync.aligned.m8n8.x4.trans.shared.b16 {%0,%1,%2,%3}, [%4];"
        : "=r"(r[0]), "=r"(r[1]), "=r"(r[2]), "=r"(r[3]) : "r"(a));
}
__device__ __forceinline__ void mma16816(float* d, const uint32_t* a, const uint32_t* b) {
    asm volatile(
        "mma.sync.aligned.m16n8k16.row.col.f32.bf16.bf16.f32 "
        "{%0,%1,%2,%3}, {%4,%5,%6,%7}, {%8,%9}, {%0,%1,%2,%3};"
        : "+f"(d[0]), "+f"(d[1]), "+f"(d[2]), "+f"(d[3])
        : "r"(a[0]), "r"(a[1]), "r"(a[2]), "r"(a[3]), "r"(b[0]), "r"(b[1]));
}
__device__ __forceinline__ void cp16(uint32_t dst, const void* src) {
    asm volatile("cp.async.cg.shared.global [%0], [%1], 16;" :: "r"(dst), "l"(src));
}
#define CP_COMMIT() asm volatile("cp.async.commit_group;")
#define CP_WAIT1()  asm volatile("cp.async.wait_group 1;")
#define CP_WAIT0()  asm volatile("cp.async.wait_group 0;")

struct alignas(16) BF8 { bf16 v[8]; };
__device__ __forceinline__ void split8(const float* f, BF8& hi, BF8& lo) {
    #pragma unroll
    for (int i = 0; i < 8; ++i) {
        bf16 h = __float2bfloat16(f[i]);
        hi.v[i] = h;
        lo.v[i] = __float2bfloat16(f[i] - __bfloat162float(h));
    }
}
__device__ __forceinline__ void split_store2(bf16* H, bf16* L, ll idx, float a, float b) {
    __nv_bfloat162 h, l;
    h.x = __float2bfloat16(a); h.y = __float2bfloat16(b);
    l.x = __float2bfloat16(a - __bfloat162float(h.x));
    l.y = __float2bfloat16(b - __bfloat162float(h.y));
    *(__nv_bfloat162*)(H + idx) = h;
    *(__nv_bfloat162*)(L + idx) = l;
}
// split-store into smem P tile (PL = PH + 34816)
__device__ __forceinline__ void split_sts2(uint8_t* ph, uint32_t off, float a, float b) {
    __nv_bfloat162 h, l;
    h.x = __float2bfloat16(a); h.y = __float2bfloat16(b);
    l.x = __float2bfloat16(a - __bfloat162float(h.x));
    l.y = __float2bfloat16(b - __bfloat162float(h.y));
    *(__nv_bfloat162*)(ph + off) = h;
    *(__nv_bfloat162*)(ph + 34816 + off) = l;
}

#define F_TRANS   1
#define F_EXP     2
#define F_OUTPAIR 8

// ---------- split prepass: 3 jobs per launch via z ----------
__global__ void __launch_bounds__(256) k_split3(
    const float* s0, bf16* h0, bf16* l0, int n0,
    const float* s1, bf16* h1, bf16* l1, int n1,
    const float* s2, bf16* h2, bf16* l2, int n2)
{
    const float* s; bf16 *h, *l; int n;
    if (blockIdx.z == 0)      { s = s0; h = h0; l = l0; n = n0; }
    else if (blockIdx.z == 1) { s = s1; h = h1; l = l1; n = n1; }
    else                      { s = s2; h = h2; l = l2; n = n2; }
    for (int i = blockIdx.x * 256 + threadIdx.x; i < n; i += gridDim.x * 256) {
        float f[8];
        *(float4*)(f)     = *(const float4*)(s + (ll)i * 8);
        *(float4*)(f + 4) = *(const float4*)(s + (ll)i * 8 + 4);
        BF8 hi, lo; split8(f, hi, lo);
        *(uint4*)(h + (ll)i * 8) = *(const uint4*)&hi;
        *(uint4*)(l + (ll)i * 8) = *(const uint4*)&lo;
    }
}
__global__ void __launch_bounds__(1024) k_pack_bias(
    const float* bq, const float* bk, const float* bv,
    const float* bmq, const float* bmk)
{
    int t = threadIdx.x;
    g_b3[t] = bq[t]; g_b3[1024 + t] = bk[t]; g_b3[2048 + t] = bv[t];
    if (t < 512) { g_bm2[t] = bmq[t]; g_bm2[512 + t] = bmk[t]; }
}

// ---------- cp.async 3-stage pre-split GEMM: CTA 128x128, 512 thr ----------
__global__ void __launch_bounds__(512, 1) k_ps(
    const bf16* __restrict__ AH, const bf16* __restrict__ AL,
    const bf16* __restrict__ BH, const bf16* __restrict__ BL,
    const float* __restrict__ bias,
    float* __restrict__ C, bf16* __restrict__ CH, bf16* __restrict__ CL,
    float* __restrict__ Psum,
    int K, int lda, int ldb, int ldc, int zdiv,
    ll sA1, ll sA0, ll sB1, ll sB0, ll sC1, ll sC0,
    ll sP1, ll sBias1,
    float alpha, int flags)
{
    extern __shared__ __align__(16) uint8_t smem[];
    const uint32_t sb = smem_to_u32(smem);
    const int tid = threadIdx.x, wid = tid >> 5, lane = tid & 31;
    const int z = blockIdx.z, z1 = z / zdiv, z0 = z % zdiv;
    AH += z1 * sA1 + z0 * sA0;  AL += z1 * sA1 + z0 * sA0;
    BH += z1 * sB1 + z0 * sB0;  BL += z1 * sB1 + z0 * sB0;
    const ll cBase = z1 * sC1 + z0 * sC0;
    const ll ziP   = z1 * sP1;
    const ll ziB   = z1 * sBias1;

    const int m0 = blockIdx.y * 128, n0 = blockIdx.x * 128;
    const int wm0 = (wid >> 2) * 32, wn0 = (wid & 3) * 32;

    const uint32_t aLane = (uint32_t)(wm0 + (lane & 15)) * 80u + (uint32_t)(lane >> 4) * 16u;
    const uint32_t bLaneNT = (uint32_t)(wn0 + ((lane >> 1) & 8) + (lane & 7)) * 80u
                           + (uint32_t)(lane & 8) * 2u;
    const uint32_t bLaneNN = (uint32_t)(lane & 15) * 272u
                           + (uint32_t)(wn0 + ((lane >> 1) & 8)) * 2u;

    const int arow = tid >> 2, akc = tid & 3;
    const int bkr  = tid >> 4, bnc = tid & 15;

    float acc[2][4][4];
    #pragma unroll
    for (int i = 0; i < 2; ++i)
        #pragma unroll
        for (int j = 0; j < 4; ++j)
            #pragma unroll
            for (int e = 0; e < 4; ++e) acc[i][j][e] = 0.0f;

#define ISSUE(itv) { \
        const int k0i = (itv) << 5; \
        const uint32_t st = sb + (uint32_t)((itv) % 3) * 40960u; \
        const ll aIdx = (ll)(m0 + arow) * lda + k0i + akc * 8; \
        cp16(st + (uint32_t)arow * 80u + (uint32_t)akc * 16u, AH + aIdx); \
        cp16(st + 10240u + (uint32_t)arow * 80u + (uint32_t)akc * 16u, AL + aIdx); \
        if (flags & F_TRANS) { \
            const ll bIdx = (ll)(n0 + arow) * ldb + k0i + akc * 8; \
            cp16(st + 20480u + (uint32_t)arow * 80u + (uint32_t)akc * 16u, BH + bIdx); \
            cp16(st + 30720u + (uint32_t)arow * 80u + (uint32_t)akc * 16u, BL + bIdx); \
        } else { \
            const ll bIdx = (ll)(k0i + bkr) * ldb + n0 + bnc * 8; \
            cp16(st + 20480u + (uint32_t)bkr * 272u + (uint32_t)bnc * 16u, BH + bIdx); \
            cp16(st + 30720u + (uint32_t)bkr * 272u + (uint32_t)bnc * 16u, BL + bIdx); \
        } }

    const int nIter = K >> 5;
    ISSUE(0); CP_COMMIT();
    ISSUE(1); CP_COMMIT();

    for (int it = 0; it < nIter; ++it) {
        if (it + 1 < nIter) { CP_WAIT1(); } else { CP_WAIT0(); }
        __syncthreads();
        if (it + 2 < nIter) ISSUE(it + 2);
        CP_COMMIT();

        const uint32_t stb = sb + (uint32_t)(it % 3) * 40960u;
        #pragma unroll
        for (int kk = 0; kk < 2; ++kk) {
            uint32_t ahi[2][4], alo[2][4], bhi[2][4], blo[2][4];
            const uint32_t akk = aLane + (uint32_t)(kk * 32);
            #pragma unroll
            for (int mi = 0; mi < 2; ++mi) {
                const uint32_t off = akk + (uint32_t)(mi * 16) * 80u;
                ldmx4(ahi[mi], stb + off);
                ldmx4(alo[mi], stb + 10240u + off);
            }
            if (flags & F_TRANS) {
                const uint32_t bkk = bLaneNT + (uint32_t)(kk * 32);
                #pragma unroll
                for (int nj = 0; nj < 2; ++nj) {
                    const uint32_t off = bkk + (uint32_t)(nj * 16) * 80u;
                    ldmx4(bhi[nj], stb + 20480u + off);
                    ldmx4(blo[nj], stb + 30720u + off);
                }
            } else {
                const uint32_t bkk = bLaneNN + (uint32_t)(kk * 16) * 272u;
                #pragma unroll
                for (int nj = 0; nj < 2; ++nj) {
                    const uint32_t off = bkk + (uint32_t)(nj * 16) * 2u;
                    ldmx4t(bhi[nj], stb + 20480u + off);
                    ldmx4t(blo[nj], stb + 30720u + off);
                }
            }
            #pragma unroll
            for (int mi = 0; mi < 2; ++mi)
                #pragma unroll
                for (int jj = 0; jj < 4; ++jj) {
                    const uint32_t* bh = &bhi[jj >> 1][(jj & 1) * 2];
                    const uint32_t* bl = &blo[jj >> 1][(jj & 1) * 2];
                    mma16816(acc[mi][jj], ahi[mi], bh);
                    mma16816(acc[mi][jj], ahi[mi], bl);
                    mma16816(acc[mi][jj], alo[mi], bh);
                }
        }
    }
    __syncthreads();
#undef ISSUE

    const int g = lane >> 2, t = lane & 3;
    if (flags & F_EXP) {
        float* rowst = (float*)smem;
        float rp[2][2] = {{0.f, 0.f}, {0.f, 0.f}};
        #pragma unroll
        for (int mi = 0; mi < 2; ++mi) {
            const ll r0 = m0 + wm0 + mi * 16 + g, r1 = r0 + 8;
            #pragma unroll
            for (int jj = 0; jj < 4; ++jj) {
                const int col = n0 + wn0 + jj * 8 + t * 2;
                const float e00 = __expf(acc[mi][jj][0] * alpha);
                const float e01 = __expf(acc[mi][jj][1] * alpha);
                const float e10 = __expf(acc[mi][jj][2] * alpha);
                const float e11 = __expf(acc[mi][jj][3] * alpha);
                *(float2*)&C[cBase + r0 * ldc + col] = make_float2(e00, e01);
                *(float2*)&C[cBase + r1 * ldc + col] = make_float2(e10, e11);
                rp[mi][0] += e00 + e01;
                rp[mi][1] += e10 + e11;
            }
        }
        const int cidx = (wid & 3) * 4 + t;
        rowst[(wm0 + g)      * 16 + cidx] = rp[0][0];
        rowst[(wm0 + g + 8)  * 16 + cidx] = rp[0][1];
        rowst[(wm0 + 16 + g) * 16 + cidx] = rp[1][0];
        rowst[(wm0 + 24 + g) * 16 + cidx] = rp[1][1];
        __syncthreads();
        if (tid < 128) {
            float s = 0.f;
            #pragma unroll
            for (int j = 0; j < 16; ++j) s += rowst[tid * 16 + j];
            Psum[(ziP + m0 + tid) * 32 + blockIdx.x] = s;
        }
    } else {
        #pragma unroll
        for (int mi = 0; mi < 2; ++mi) {
            #pragma unroll
            for (int jj = 0; jj < 4; ++jj) {
                const ll r0 = m0 + wm0 + mi * 16 + g, r1 = r0 + 8;
                const int col = n0 + wn0 + jj * 8 + t * 2;
                float v00 = acc[mi][jj][0], v01 = acc[mi][jj][1];
                float v10 = acc[mi][jj][2], v11 = acc[mi][jj][3];
                if (bias) {
                    const float b0 = bias[ziB + col], b1 = bias[ziB + col + 1];
                    v00 += b0; v01 += b1; v10 += b0; v11 += b1;
                }
                if (flags & F_OUTPAIR) {
                    split_store2(CH, CL, cBase + r0 * ldc + col, v00, v01);
                    split_store2(CH, CL, cBase + r1 * ldc + col, v10, v11);
                } else {
                    *(float2*)&C[cBase + r0 * ldc + col] = make_float2(v00, v01);
                    *(float2*)&C[cBase + r1 * ldc + col] = make_float2(v10, v11);
                }
            }
        }
    }
}

// ---------- attn pass 1: full-row exp sums -> pinv (no probs store) ----------
// smem: QH 0, QL 18432, KH 36864, KL 55296; rowst reuses base. 81920 B.
__global__ void __launch_bounds__(512, 1) k_asum(
    const bf16* __restrict__ qH, const bf16* __restrict__ qL,
    const bf16* __restrict__ kH, const bf16* __restrict__ kL,
    const float* __restrict__ med, const float* __restrict__ minv,
    float* __restrict__ pinv)
{
    extern __shared__ __align__(16) uint8_t smem[];
    const uint32_t sb = smem_to_u32(smem);
    const int tid = threadIdx.x, wid = tid >> 5, lane = tid & 31;
    const int z = blockIdx.z, b = z >> 4, h = z & 15;
    const int m0 = blockIdx.y * 128;
    const bf16* qh = qH + (ll)b * 2097152 + h * 64;
    const bf16* ql = qL + (ll)b * 2097152 + h * 64;
    const bf16* kh = kH + (ll)b * 2097152 + h * 64;
    const bf16* kl = kL + (ll)b * 2097152 + h * 64;
    const float* medb = med + (ll)b * 4194304;
    const float* mib  = minv + (ll)b * 2048;

    const int wm0 = (wid >> 2) * 32, wn0 = (wid & 3) * 32;
    const uint32_t aLane = (uint32_t)(wm0 + (lane & 15)) * 144u + (uint32_t)(lane >> 4) * 16u;
    const uint32_t bLane = (uint32_t)(wn0 + ((lane >> 1) & 8) + (lane & 7)) * 144u
                         + (uint32_t)(lane & 8) * 2u;
    const int grow = tid >> 2, gch = tid & 3;

#define Q_ISSUE() { \
        _Pragma("unroll") for (int c2 = 0; c2 < 2; ++c2) { \
            const int c = gch + c2 * 4; \
            const ll idx = (ll)(m0 + grow) * 1024 + c * 8; \
            cp16(sb + (uint32_t)grow * 144u + (uint32_t)c * 16u, qh + idx); \
            cp16(sb + 18432u + (uint32_t)grow * 144u + (uint32_t)c * 16u, ql + idx); \
        } }
#define K_ISSUE(nt) { \
        const int nb = (nt) * 128; \
        _Pragma("unroll") for (int c2 = 0; c2 < 2; ++c2) { \
            const int c = gch + c2 * 4; \
            const ll idx = (ll)(nb + grow) * 1024 + c * 8; \
            cp16(sb + 36864u + (uint32_t)grow * 144u + (uint32_t)c * 16u, kh + idx); \
            cp16(sb + 55296u + (uint32_t)grow * 144u + (uint32_t)c * 16u, kl + idx); \
        } }

    Q_ISSUE(); K_ISSUE(0); CP_COMMIT();

    const int g = lane >> 2, t = lane & 3;
    float ai[2][2], rp[2][2] = {{0.f, 0.f}, {0.f, 0.f}};
    #pragma unroll
    for (int mi = 0; mi < 2; ++mi) {
        ai[mi][0] = mib[m0 + wm0 + mi * 16 + g] * 0.3f;
        ai[mi][1] = mib[m0 + wm0 + mi * 16 + g + 8] * 0.3f;
    }

    for (int nt = 0; nt < 16; ++nt) {
        CP_WAIT0();
        __syncthreads();
        float acc[2][4][4];
        #pragma unroll
        for (int i = 0; i < 2; ++i)
            #pragma unroll
            for (int j = 0; j < 4; ++j)
                #pragma unroll
                for (int e = 0; e < 4; ++e) acc[i][j][e] = 0.0f;
        #pragma unroll
        for (int kk = 0; kk < 4; ++kk) {
            uint32_t ahi[2][4], alo[2][4], bhi[2][4], blo[2][4];
            const uint32_t akk = aLane + (uint32_t)(kk * 32);
            #pragma unroll
            for (int mi = 0; mi < 2; ++mi) {
                const uint32_t off = akk + (uint32_t)(mi * 16) * 144u;
                ldmx4(ahi[mi], sb + off);
                ldmx4(alo[mi], sb + 18432u + off);
            }
            const uint32_t bkk = bLane + (uint32_t)(kk * 32);
            #pragma unroll
            for (int nj = 0; nj < 2; ++nj) {
                const uint32_t off = bkk + (uint32_t)(nj * 16) * 144u;
                ldmx4(bhi[nj], sb + 36864u + off);
                ldmx4(blo[nj], sb + 55296u + off);
            }
            #pragma unroll
            for (int mi = 0; mi < 2; ++mi)
                #pragma unroll
                for (int jj = 0; jj < 4; ++jj) {
                    const uint32_t* bh = &bhi[jj >> 1][(jj & 1) * 2];
                    const uint32_t* bl = &blo[jj >> 1][(jj & 1) * 2];
                    mma16816(acc[mi][jj], ahi[mi], bh);
                    mma16816(acc[mi][jj], ahi[mi], bl);
                    mma16816(acc[mi][jj], alo[mi], bh);
                }
        }
        __syncthreads();
        if (nt < 15) { K_ISSUE(nt + 1); }
        CP_COMMIT();

        const int n0 = nt * 128;
        #pragma unroll
        for (int mi = 0; mi < 2; ++mi) {
            const ll r0 = m0 + wm0 + mi * 16 + g, r1 = r0 + 8;
            #pragma unroll
            for (int jj = 0; jj < 4; ++jj) {
                const int col = n0 + wn0 + jj * 8 + t * 2;
                float2 a0 = *(const float2*)&medb[r0 * 2048 + col];
                float2 a1 = *(const float2*)&medb[r1 * 2048 + col];
                rp[mi][0] += __expf(acc[mi][jj][0] * 0.125f + ai[mi][0] * a0.x)
                           + __expf(acc[mi][jj][1] * 0.125f + ai[mi][0] * a0.y);
                rp[mi][1] += __expf(acc[mi][jj][2] * 0.125f + ai[mi][1] * a1.x)
                           + __expf(acc[mi][jj][3] * 0.125f + ai[mi][1] * a1.y);
            }
        }
    }
    __syncthreads();
    float* rowst = (float*)smem;
    const int cidx = (wid & 3) * 4 + t;
    rowst[(wm0 + g)      * 16 + cidx] = rp[0][0];
    rowst[(wm0 + g + 8)  * 16 + cidx] = rp[0][1];
    rowst[(wm0 + 16 + g) * 16 + cidx] = rp[1][0];
    rowst[(wm0 + 24 + g) * 16 + cidx] = rp[1][1];
    __syncthreads();
    if (tid < 128) {
        float s = 0.f;
        #pragma unroll
        for (int j = 0; j < 16; ++j) s += rowst[tid * 16 + j];
        pinv[(ll)z * 2048 + m0 + tid] = 1.0f / s;
    }
#undef Q_ISSUE
#undef K_ISSUE
}

// ---------- attn pass 2: recompute, write normalized probs ONCE, fused ctx ----
// smem: QH 0, QL 18432, KH 36864, KL 55296, PH 73728 (stride 272, 34816),
//       PL 108544, V bufs at 143360 + (nt&1)*36864 (VH +0, VL +18432). 217088 B.
__global__ void __launch_bounds__(512, 1) k_actx(
    const bf16* __restrict__ qH, const bf16* __restrict__ qL,
    const bf16* __restrict__ kH, const bf16* __restrict__ kL,
    const bf16* __restrict__ vH, const bf16* __restrict__ vL,
    const float* __restrict__ med, const float* __restrict__ minv,
    const float* __restrict__ pinv,
    float* __restrict__ probs, bf16* __restrict__ catH, bf16* __restrict__ catL)
{
    extern __shared__ __align__(16) uint8_t smem[];
    const uint32_t sb = smem_to_u32(smem);
    const int tid = threadIdx.x, wid = tid >> 5, lane = tid & 31;
    const int z = blockIdx.z, b = z >> 4, h = z & 15;
    const int m0 = blockIdx.y * 128;
    const bf16* qh = qH + (ll)b * 2097152 + h * 64;
    const bf16* ql = qL + (ll)b * 2097152 + h * 64;
    const bf16* kh = kH + (ll)b * 2097152 + h * 64;
    const bf16* kl = kL + (ll)b * 2097152 + h * 64;
    const bf16* vh = vH + (ll)b * 2097152 + h * 64;
    const bf16* vl = vL + (ll)b * 2097152 + h * 64;
    const float* medb = med + (ll)b * 4194304;
    const float* mib  = minv + (ll)b * 2048;
    const float* pvz  = pinv + (ll)z * 2048;
    float* pz = probs + (ll)z * 4194304;
    catH += (ll)b * 3145728 + h * 64;
    catL += (ll)b * 3145728 + h * 64;

    const int wm0 = (wid >> 2) * 32, wn0 = (wid & 3) * 32, wn0c = (wid & 3) * 16;
    const uint32_t aLane = (uint32_t)(wm0 + (lane & 15)) * 144u + (uint32_t)(lane >> 4) * 16u;
    const uint32_t bLane = (uint32_t)(wn0 + ((lane >> 1) & 8) + (lane & 7)) * 144u
                         + (uint32_t)(lane & 8) * 2u;
    const uint32_t aLaneP = (uint32_t)(wm0 + (lane & 15)) * 272u + (uint32_t)(lane >> 4) * 16u;
    const uint32_t bLaneV = (uint32_t)(lane & 15) * 144u
                          + (uint32_t)(wn0c + ((lane >> 1) & 8)) * 2u;
    const int grow = tid >> 2, gch = tid & 3;

#define Q_ISSUE() { \
        _Pragma("unroll") for (int c2 = 0; c2 < 2; ++c2) { \
            const int c = gch + c2 * 4; \
            const ll idx = (ll)(m0 + grow) * 1024 + c * 8; \
            cp16(sb + (uint32_t)grow * 144u + (uint32_t)c * 16u, qh + idx); \
            cp16(sb + 18432u + (uint32_t)grow * 144u + (uint32_t)c * 16u, ql + idx); \
        } }
#define K_ISSUE(nt) { \
        const int nb = (nt) * 128; \
        _Pragma("unroll") for (int c2 = 0; c2 < 2; ++c2) { \
            const int c = gch + c2 * 4; \
            const ll idx = (ll)(nb + grow) * 1024 + c * 8; \
            cp16(sb + 36864u + (uint32_t)grow * 144u + (uint32_t)c * 16u, kh + idx); \
            cp16(sb + 55296u + (uint32_t)grow * 144u + (uint32_t)c * 16u, kl + idx); \
        } }
#define V_ISSUE(nt) { \
        const uint32_t vb = sb + 143360u + (uint32_t)((nt) & 1) * 36864u; \
        const int nb = (nt) * 128; \
        _Pragma("unroll") for (int c2 = 0; c2 < 2; ++c2) { \
            const int c = gch + c2 * 4; \
            const ll idx = (ll)(nb + grow) * 1024 + c * 8; \
            cp16(vb + (uint32_t)grow * 144u + (uint32_t)c * 16u, vh + idx); \
            cp16(vb + 18432u + (uint32_t)grow * 144u + (uint32_t)c * 16u, vl + idx); \
        } }

    Q_ISSUE(); K_ISSUE(0); V_ISSUE(0); CP_COMMIT();

    const int g = lane >> 2, t = lane & 3;
    float ai[2][2], pv[2][2];
    #pragma unroll
    for (int mi = 0; mi < 2; ++mi) {
        const int r0l = m0 + wm0 + mi * 16 + g;
        ai[mi][0] = mib[r0l] * 0.3f;      ai[mi][1] = mib[r0l + 8] * 0.3f;
        pv[mi][0] = pvz[r0l];             pv[mi][1] = pvz[r0l + 8];
    }

    float acc2[2][2][4];
    #pragma unroll
    for (int i = 0; i < 2; ++i)
        #pragma unroll
        for (int j = 0; j < 2; ++j)
            #pragma unroll
            for (int e = 0; e < 4; ++e) acc2[i][j][e] = 0.0f;

    uint8_t* PH = smem + 73728;

    for (int nt = 0; nt < 16; ++nt) {
        CP_WAIT0();
        __syncthreads();

        // ---- scores MMA
        float acc[2][4][4];
        #pragma unroll
        for (int i = 0; i < 2; ++i)
            #pragma unroll
            for (int j = 0; j < 4; ++j)
                #pragma unroll
                for (int e = 0; e < 4; ++e) acc[i][j][e] = 0.0f;
        #pragma unroll
        for (int kk = 0; kk < 4; ++kk) {
            uint32_t ahi[2][4], alo[2][4], bhi[2][4], blo[2][4];
            const uint32_t akk = aLane + (uint32_t)(kk * 32);
            #pragma unroll
            for (int mi = 0; mi < 2; ++mi) {
                const uint32_t off = akk + (uint32_t)(mi * 16) * 144u;
                ldmx4(ahi[mi], sb + off);
                ldmx4(alo[mi], sb + 18432u + off);
            }
            const uint32_t bkk = bLane + (uint32_t)(kk * 32);
            #pragma unroll
            for (int nj = 0; nj < 2; ++nj) {
                const uint32_t off = bkk + (uint32_t)(nj * 16) * 144u;
                ldmx4(bhi[nj], sb + 36864u + off);
                ldmx4(blo[nj], sb + 55296u + off);
            }
            #pragma unroll
            for (int mi = 0; mi < 2; ++mi)
                #pragma unroll
                for (int jj = 0; jj < 4; ++jj) {
                    const uint32_t* bh = &bhi[jj >> 1][(jj & 1) * 2];
                    const uint32_t* bl = &blo[jj >> 1][(jj & 1) * 2];
                    mma16816(acc[mi][jj], ahi[mi], bh);
                    mma16816(acc[mi][jj], ahi[mi], bl);
                    mma16816(acc[mi][jj], alo[mi], bh);
                }
        }
        __syncthreads();
        if (nt < 15) { K_ISSUE(nt + 1); V_ISSUE(nt + 1); }
        CP_COMMIT();

        // ---- epilogue: normalized e -> probs (only write) + P smem tile
        const int n0 = nt * 128;
        #pragma unroll
        for (int mi = 0; mi < 2; ++mi) {
            const ll r0 = m0 + wm0 + mi * 16 + g, r1 = r0 + 8;
            const uint32_t pr0 = (uint32_t)(wm0 + mi * 16 + g) * 272u;
            const uint32_t pr1 = pr0 + 8u * 272u;
            #pragma unroll
            for (int jj = 0; jj < 4; ++jj) {
                const int col = n0 + wn0 + jj * 8 + t * 2;
                const uint32_t colLoc = (uint32_t)(wn0 + jj * 8 + t * 2) * 2u;
                float2 a0 = *(const float2*)&medb[r0 * 2048 + col];
                float2 a1 = *(const float2*)&medb[r1 * 2048 + col];
                const float e00 = __expf(acc[mi][jj][0] * 0.125f + ai[mi][0] * a0.x) * pv[mi][0];
                const float e01 = __expf(acc[mi][jj][1] * 0.125f + ai[mi][0] * a0.y) * pv[mi][0];
                const float e10 = __expf(acc[mi][jj][2] * 0.125f + ai[mi][1] * a1.x) * pv[mi][1];
                const float e11 = __expf(acc[mi][jj][3] * 0.125f + ai[mi][1] * a1.y) * pv[mi][1];
                *(float2*)&pz[r0 * 2048 + col] = make_float2(e00, e01);
                *(float2*)&pz[r1 * 2048 + col] = make_float2(e10, e11);
                split_sts2(PH, pr0 + colLoc, e00, e01);
                split_sts2(PH, pr1 + colLoc, e10, e11);
            }
        }
        __syncthreads();

        // ---- ctx MMA: P[128m x 128k] @ V[128k x 64n]
        const uint32_t vb = sb + 143360u + (uint32_t)(nt & 1) * 36864u;
        #pragma unroll
        for (int kk = 0; kk < 8; ++kk) {
            uint32_t phi[2][4], plo[2][4], vhi[4], vlo[4];
            const uint32_t akk = aLaneP + (uint32_t)(kk * 32);
            #pragma unroll
            for (int mi = 0; mi < 2; ++mi) {
                const uint32_t off = akk + (uint32_t)(mi * 16) * 272u;
                ldmx4(phi[mi], sb + 73728u + off);
                ldmx4(plo[mi], sb + 108544u + off);
            }
            const uint32_t bkk = bLaneV + (uint32_t)(kk * 16) * 144u;
            ldmx4t(vhi, vb + bkk);
            ldmx4t(vlo, vb + 18432u + bkk);
            #pragma unroll
            for (int mi = 0; mi < 2; ++mi)
                #pragma unroll
                for (int jj = 0; jj < 2; ++jj) {
                    mma16816(acc2[mi][jj], phi[mi], &vhi[jj * 2]);
                    mma16816(acc2[mi][jj], phi[mi], &vlo[jj * 2]);
                    mma16816(acc2[mi][jj], plo[mi], &vhi[jj * 2]);
                }
        }
    }

    // ---- cat epilogue (already normalized)
    #pragma unroll
    for (int mi = 0; mi < 2; ++mi) {
        #pragma unroll
        for (int jj = 0; jj < 2; ++jj) {
            const ll r0 = m0 + wm0 + mi * 16 + g, r1 = r0 + 8;
            const int colc = wn0c + jj * 8 + t * 2;
            split_store2(catH, catL, r0 * 1536 + colc, acc2[mi][jj][0], acc2[mi][jj][1]);
            split_store2(catH, catL, r1 * 1536 + colc, acc2[mi][jj][2], acc2[mi][jj][3]);
        }
    }
#undef Q_ISSUE
#undef K_ISSUE
#undef V_ISSUE
}

// ---------- row partial sums -> inverse (med only) ----------
__global__ void __launch_bounds__(256) k_rowinv(
    const float* __restrict__ part, float* __restrict__ inv, int ncols)
{
    const int row = blockIdx.x * 8 + (threadIdx.x >> 5);
    const int lane = threadIdx.x & 31;
    float s = (lane < ncols) ? part[(ll)row * 32 + lane] : 0.f;
    #pragma unroll
    for (int o = 16; o; o >>= 1) s += __shfl_xor_sync(0xFFFFFFFFu, s, o);
    if (lane == 0) inv[row] = 1.0f / s;
}

// ---------- residual + LayerNorm ----------
__global__ void __launch_bounds__(256) k_ln_res(
    const float* __restrict__ xin, const float* __restrict__ hs,
    const float* __restrict__ g, const float* __restrict__ be,
    float* __restrict__ out)
{
    ll row = blockIdx.x;
    const float* xr = xin + row * H_;
    const float* hr = hs + row * H_;
    float* orow = out + row * H_;
    int tid = threadIdx.x;
    __shared__ float red[256];
    float v[4]; float s = 0.0f;
    #pragma unroll
    for (int i = 0; i < 4; ++i) { v[i] = xr[tid + i * 256] + hr[tid + i * 256]; s += v[i]; }
    red[tid] = s; __syncthreads();
    for (int tt = 128; tt > 0; tt >>= 1) {
        if (tid < tt) red[tid] += red[tid + tt];
        __syncthreads();
    }
    float mu = red[0] * (1.0f / H_); __syncthreads();
    float var = 0.0f;
    #pragma unroll
    for (int i = 0; i < 4; ++i) { float d = v[i] - mu; var += d * d; }
    red[tid] = var; __syncthreads();
    for (int tt = 128; tt > 0; tt >>= 1) {
        if (tid < tt) red[tid] += red[tid + tt];
        __syncthreads();
    }
    float inv = rsqrtf(red[0] * (1.0f / H_) + 1e-12f);
    #pragma unroll
    for (int i = 0; i < 4; ++i) {
        int c = tid + i * 256;
        orow[c] = (v[i] - mu) * inv * g[c] + be[c];
    }
}

// ---------- launch ----------
extern "C" void kernel_launch(void* const* d_in, const int* in_sizes, int n_in,
                              void* d_out, int out_size)
{
    const float* hs  = (const float*)d_in[0];
    const float* mc  = (const float*)d_in[1];
    const float* Wq  = (const float*)d_in[2];  const float* bq  = (const float*)d_in[3];
    const float* Wk  = (const float*)d_in[4];  const float* bk  = (const float*)d_in[5];
    const float* Wv  = (const float*)d_in[6];  const float* bv  = (const float*)d_in[7];
    const float* Wmq = (const float*)d_in[8];  const float* bmq = (const float*)d_in[9];
    const float* Wmk = (const float*)d_in[10]; const float* bmk = (const float*)d_in[11];
    const float* Wc  = (const float*)d_in[12]; const float* bc  = (const float*)d_in[13];
    const float* Wf  = (const float*)d_in[14]; const float* bf  = (const float*)d_in[15];
    const float* lg  = (const float*)d_in[16]; const float* lb  = (const float*)d_in[17];

    float* out   = (float*)d_out;
    float* probs = out + (ll)B_ * S_ * H_;

    bf16 *inH,*inL,*wH,*wL,*wmH,*wmL,*wcH,*wcL,*wfH,*wfL,*qkvH,*qkvL,*mqkH,*mqkL,*catH,*catL;
    float *b3,*bm2,*med,*x,*part,*minv,*pinv;
    cudaGetSymbolAddress((void**)&inH,  g_inH);  cudaGetSymbolAddress((void**)&inL,  g_inL);
    cudaGetSymbolAddress((void**)&wH,   g_wH);   cudaGetSymbolAddress((void**)&wL,   g_wL);
    cudaGetSymbolAddress((void**)&wmH,  g_wmH);  cudaGetSymbolAddress((void**)&wmL,  g_wmL);
    cudaGetSymbolAddress((void**)&wcH,  g_wcH);  cudaGetSymbolAddress((void**)&wcL,  g_wcL);
    cudaGetSymbolAddress((void**)&wfH,  g_wfH);  cudaGetSymbolAddress((void**)&wfL,  g_wfL);
    cudaGetSymbolAddress((void**)&qkvH, g_qkvH); cudaGetSymbolAddress((void**)&qkvL, g_qkvL);
    cudaGetSymbolAddress((void**)&mqkH, g_mqkH); cudaGetSymbolAddress((void**)&mqkL, g_mqkL);
    cudaGetSymbolAddress((void**)&catH, g_catH); cudaGetSymbolAddress((void**)&catL, g_catL);
    cudaGetSymbolAddress((void**)&b3,   g_b3);   cudaGetSymbolAddress((void**)&bm2,  g_bm2);
    cudaGetSymbolAddress((void**)&med,  g_med);  cudaGetSymbolAddress((void**)&x,    g_x);
    cudaGetSymbolAddress((void**)&part, g_part); cudaGetSymbolAddress((void**)&minv, g_minv);
    cudaGetSymbolAddress((void**)&pinv, g_pinv);

    static bool attrSet = false;
    if (!attrSet) {
        cudaFuncSetAttribute(k_ps,   cudaFuncAttributeMaxDynamicSharedMemorySize, 122880);
        cudaFuncSetAttribute(k_asum, cudaFuncAttributeMaxDynamicSharedMemorySize, 81920);
        cudaFuncSetAttribute(k_actx, cudaFuncAttributeMaxDynamicSharedMemorySize, 217088);
        attrSet = true;
    }

    const ll SS = 4194304, SM = 1048576;

    // prepass splits (3 jobs per launch)
    k_split3<<<dim3(512,1,3),256>>>(hs,  inH, inL, 524288,
                                    mc,  inH + 4194304, inL + 4194304, 524288,
                                    Wq,  wH, wL, 131072);
    k_split3<<<dim3(512,1,3),256>>>(Wk,  wH + 1048576, wL + 1048576, 131072,
                                    Wv,  wH + 2097152, wL + 2097152, 131072,
                                    Wmq, wmH, wmL, 65536);
    k_split3<<<dim3(512,1,3),256>>>(Wmk, wmH + 524288, wmL + 524288, 65536,
                                    Wc,  wcH, wcL, 65536,
                                    Wf,  wfH, wfL, 196608);
    k_pack_bias<<<1,1024>>>(bq, bk, bv, bmq, bmk);

    // QKV batched z=3 (NN, pair out)
    k_ps<<<dim3(8,32,3),512,122880>>>(inH, inL, wH, wL, b3,
        0, qkvH, qkvL, 0, 1024, 1024, 1024, 1024, 1,
        0,0, 1048576,0, 4194304,0, 0, 1024, 1.f, F_OUTPAIR);

    // mq|mk batched z=2 (NN, pair out)
    k_ps<<<dim3(4,32,2),512,122880>>>(inH, inL, wmH, wmL, bm2,
        0, mqkH, mqkL, 0, 1024, 1024, 512, 512, 1,
        4194304,0, 524288,0, 2097152,0, 0, 512, 1.f, F_OUTPAIR);

    // med scores z=2=batch (NT, exp fp32 out + Psum)
    k_ps<<<dim3(16,16,2),512,122880>>>(mqkH, mqkL, mqkH + 2097152, mqkL + 2097152, 0,
        med, 0, 0, part, 512, 512, 512, 2048, 1,
        SM,0, SM,0, SS,0, 2048, 0, 1.f, F_TRANS | F_EXP);
    k_rowinv<<<512,256>>>(part, minv, 16);

    // attn pass 1: full-row exp sums -> pinv
    k_asum<<<dim3(1,16,32),512,81920>>>(qkvH, qkvL, qkvH + 4194304, qkvL + 4194304,
                                        med, minv, pinv);

    // attn pass 2: recompute + normalized probs write + fused ctx -> cat
    k_actx<<<dim3(1,16,32),512,217088>>>(qkvH, qkvL, qkvH + 4194304, qkvL + 4194304,
                                         qkvH + 8388608, qkvL + 8388608,
                                         med, minv, pinv, probs, catH, catL);

    // clin (NN, pair out into cat cols 1024:1536)
    k_ps<<<dim3(4,32,1),512,122880>>>(catH, catL, wcH, wcL, bc,
        0, catH + 1024, catL + 1024, 0, 1024, 1536, 512, 1536, 1,
        0,0, 0,0, 0,0, 0, 0, 1.f, F_OUTPAIR);

    // final (NN, fp32 out)
    k_ps<<<dim3(8,32,1),512,122880>>>(catH, catL, wfH, wfL, bf,
        x, 0, 0, 0, 1536, 1536, 1024, 1024, 1,
        0,0, 0,0, 0,0, 0, 0, 1.f, 0);

    k_ln_res<<<4096,256>>>(x, hs, lg, lb, out);
}